// round 5
// baseline (speedup 1.0000x reference)
#include <cuda_runtime.h>
#include <float.h>
#include <math.h>

#define B_     2
#define RESO_  32
#define G_     (RESO_*RESO_*RESO_)
#define BG_    (B_*G_)                 /* 65536 */
#define HID_   32
#define NMAX_  524288
#define BDIM   128

typedef unsigned long long u64;
typedef unsigned int u32;

__device__ __forceinline__ u64 splat2(float v) {
    u64 r; asm("mov.b64 %0, {%1, %1};" : "=l"(r) : "f"(v)); return r;
}
__device__ __forceinline__ void unpack2(u64 v, float& lo, float& hi) {
    asm("mov.b64 {%0, %1}, %2;" : "=f"(lo), "=f"(hi) : "l"(v));
}
__device__ __forceinline__ void ffma2(u64& d, u64 a, u64 b) {
    asm("fma.rn.f32x2 %0, %1, %2, %0;" : "+l"(d) : "l"(a), "l"(b));
}

/* monotone float<->uint map: unsigned compare order == float order */
__device__ __forceinline__ u32 fmap(float v) {
    u32 u = __float_as_uint(v);
    return (u & 0x80000000u) ? ~u : (u | 0x80000000u);
}
__device__ __forceinline__ float funmap(u32 u) {
    return __uint_as_float((u & 0x80000000u) ? (u ^ 0x80000000u) : ~u);
}

/* -------- scratch -------- */
__device__ float g_net[(size_t)NMAX_*HID_];   /* by sorted slot */
__device__ int   g_gidx[NMAX_];               /* by orig index  */
__device__ int   g_perm[NMAX_];               /* slot -> orig   */
__device__ int   g_sgidx[NMAX_];              /* slot -> gidx   */
__device__ int   g_hist[BG_];
__device__ int   g_cursor[BG_];
__device__ u32   g_cellA[BG_*HID_];
__device__ u32   g_cellB[BG_*HID_];
__device__ float g_sums[BG_*HID_];

/* -------- sort pre-pass -------- */
__global__ void zero_hist_kernel() {
    int s = gridDim.x*blockDim.x;
    for (int i = blockIdx.x*blockDim.x + threadIdx.x; i < BG_; i += s) g_hist[i] = 0;
}
__global__ void index_hist_kernel(const float* __restrict__ p, int T, int N) {
    int i = blockIdx.x*blockDim.x + threadIdx.x;
    if (i >= N) return;
    float p0 = p[3*i+0], p1 = p[3*i+1], p2 = p[3*i+2];
    int b = i / T;
    float pn0 = fminf(fmaxf(__fdiv_rn(p0, 1.101f) + 0.5f, 0.0f), 0.999f);
    float pn1 = fminf(fmaxf(__fdiv_rn(p1, 1.101f) + 0.5f, 0.0f), 0.999f);
    float pn2 = fminf(fmaxf(__fdiv_rn(p2, 1.101f) + 0.5f, 0.0f), 0.999f);
    int gidx = (int)floorf(pn0*32.f) + RESO_*((int)floorf(pn1*32.f) + RESO_*(int)floorf(pn2*32.f)) + b*G_;
    g_gidx[i] = gidx;
    atomicAdd(&g_hist[gidx], 1);
}
__global__ void scan_kernel() {               /* 1 block, 1024 thr, 64 bins each */
    __shared__ int part[1024];
    int t = threadIdx.x, base = t*64, s = 0;
#pragma unroll
    for (int j = 0; j < 64; j++) s += g_hist[base+j];
    part[t] = s; __syncthreads();
    for (int off = 1; off < 1024; off <<= 1) {
        int v = (t >= off) ? part[t-off] : 0;
        __syncthreads(); part[t] += v; __syncthreads();
    }
    int run = (t == 0) ? 0 : part[t-1];
#pragma unroll
    for (int j = 0; j < 64; j++) { int c = g_hist[base+j]; g_cursor[base+j] = run; run += c; }
}
__global__ void perm_kernel(int N) {
    int i = blockIdx.x*blockDim.x + threadIdx.x;
    if (i >= N) return;
    int gidx = g_gidx[i];
    int slot = atomicAdd(&g_cursor[gidx], 1);
    g_perm[slot] = i;
    g_sgidx[slot] = gidx;
}

/* -------- inits -------- */
__global__ void init_cells_kernel(int which) {
    u32* ptr = which ? g_cellB : g_cellA;
    int s = gridDim.x*blockDim.x;
    for (int i = blockIdx.x*blockDim.x + threadIdx.x; i < BG_*HID_; i += s) ptr[i] = 0u;
}
__global__ void clear_sums_kernel() {
    int s = gridDim.x*blockDim.x;
    for (int i = blockIdx.x*blockDim.x + threadIdx.x; i < BG_*HID_; i += s) g_sums[i] = 0.f;
}

/* -------- residual block (packed f32x2) -------- */
__device__ __forceinline__ void resblock_f32x2(
    const float* sx, int tid,
    const float* __restrict__ sW0, const float* __restrict__ sB0,
    const float* __restrict__ sW1, const float* __restrict__ sB1,
    const float* __restrict__ sWs, float* out)
{
    u64 h2[16], o2[16];
    const u64* b0p = reinterpret_cast<const u64*>(sB0);
    const u64* b1p = reinterpret_cast<const u64*>(sB1);
#pragma unroll
    for (int j = 0; j < 16; j++) { h2[j] = b0p[j]; o2[j] = b1p[j]; }
#pragma unroll 4
    for (int k = 0; k < 64; k++) {
        float xk = sx[k*BDIM + tid];
        u64 xk2 = splat2(xk);
        u64 xr2 = splat2(fmaxf(xk, 0.0f));
        const ulonglong2* r0 = reinterpret_cast<const ulonglong2*>(sW0 + k*HID_);
        const ulonglong2* rs = reinterpret_cast<const ulonglong2*>(sWs + k*HID_);
#pragma unroll
        for (int j = 0; j < 8; j++) {
            ulonglong2 a = r0[j], s = rs[j];
            ffma2(h2[2*j+0], xr2, a.x); ffma2(h2[2*j+1], xr2, a.y);
            ffma2(o2[2*j+0], xk2, s.x); ffma2(o2[2*j+1], xk2, s.y);
        }
    }
    float hr[HID_];
#pragma unroll
    for (int j = 0; j < 16; j++) {
        float lo, hi; unpack2(h2[j], lo, hi);
        hr[2*j+0] = fmaxf(lo, 0.0f); hr[2*j+1] = fmaxf(hi, 0.0f);
    }
#pragma unroll
    for (int k = 0; k < HID_; k++) {
        u64 hk2 = splat2(hr[k]);
        const ulonglong2* r1 = reinterpret_cast<const ulonglong2*>(sW1 + k*HID_);
#pragma unroll
        for (int j = 0; j < 8; j++) {
            ulonglong2 a = r1[j];
            ffma2(o2[2*j+0], hk2, a.x); ffma2(o2[2*j+1], hk2, a.y);
        }
    }
#pragma unroll
    for (int j = 0; j < 16; j++) unpack2(o2[j], out[2*j], out[2*j+1]);
}

__device__ __forceinline__ void scatter_max(u32* cell, int gidx, const float* out) {
    u32* cd = cell + gidx*HID_;
#pragma unroll
    for (int j = 0; j < HID_; j++) atomicMax(cd + j, fmap(out[j]));
}

/* -------- stage 0 -------- */
__global__ void __launch_bounds__(BDIM) point0_kernel(
    const float* __restrict__ p,
    const float* __restrict__ Wp, const float* __restrict__ Bp,
    const float* __restrict__ w0, const float* __restrict__ b0,
    const float* __restrict__ w1, const float* __restrict__ b1,
    const float* __restrict__ ws, int N)
{
    extern __shared__ float smem[];
    float* sWp = smem;
    float* sW0 = sWp + 60*64;
    float* sWs = sW0 + 64*HID_;
    float* sW1 = sWs + 64*HID_;
    float* sBp = sW1 + HID_*HID_;
    float* sB0 = sBp + 64;
    float* sB1 = sB0 + HID_;
    float* sx  = sB1 + HID_;

    for (int t = threadIdx.x; t < 60*64; t += BDIM) sWp[t] = Wp[t];
    for (int t = threadIdx.x; t < 64*HID_; t += BDIM) { sW0[t] = w0[t]; sWs[t] = ws[t]; }
    for (int t = threadIdx.x; t < HID_*HID_; t += BDIM) sW1[t] = w1[t];
    for (int t = threadIdx.x; t < 64; t += BDIM) sBp[t] = Bp[t];
    for (int t = threadIdx.x; t < HID_; t += BDIM) { sB0[t] = b0[t]; sB1[t] = b1[t]; }
    __syncthreads();

    int slot = blockIdx.x*BDIM + threadIdx.x;
    if (slot >= N) return;
    int tid = threadIdx.x;
    int i = g_perm[slot];
    int gidx = g_sgidx[slot];

    float p0 = p[3*i+0], p1 = p[3*i+1], p2 = p[3*i+2];

    u64 x2[32];
    const u64* bp2 = reinterpret_cast<const u64*>(sBp);
#pragma unroll
    for (int j = 0; j < 32; j++) x2[j] = bp2[j];

    float q[3] = {2.0f*p0 - 1.0f, 2.0f*p1 - 1.0f, 2.0f*p2 - 1.0f};
#pragma unroll
    for (int d = 0; d < 3; d++) {
        float y = q[d];
#pragma unroll 1
        for (int l = 0; l < 10; l++) {
            float s, c;
            sincospif(y, &s, &c);
            u64 s2 = splat2(s), c2 = splat2(c);
            const ulonglong2* rs_ = reinterpret_cast<const ulonglong2*>(sWp + (l*6 + d)*64);
            const ulonglong2* rc_ = reinterpret_cast<const ulonglong2*>(sWp + (l*6 + 3 + d)*64);
#pragma unroll
            for (int j = 0; j < 16; j++) {
                ulonglong2 a = rs_[j], bb = rc_[j];
                ffma2(x2[2*j+0], s2, a.x); ffma2(x2[2*j+1], s2, a.y);
                ffma2(x2[2*j+0], c2, bb.x); ffma2(x2[2*j+1], c2, bb.y);
            }
            y *= 2.0f;
        }
    }
#pragma unroll
    for (int j = 0; j < 32; j++) {
        float lo, hi; unpack2(x2[j], lo, hi);
        sx[(2*j+0)*BDIM + tid] = lo;
        sx[(2*j+1)*BDIM + tid] = hi;
    }

    float out[HID_];
    resblock_f32x2(sx, tid, sW0, sB0, sW1, sB1, sWs, out);

    float4* nw = reinterpret_cast<float4*>(&g_net[(size_t)slot*HID_]);
#pragma unroll
    for (int j = 0; j < 8; j++)
        nw[j] = make_float4(out[4*j], out[4*j+1], out[4*j+2], out[4*j+3]);

    scatter_max(g_cellA, gidx, out);
}

/* -------- stages 1..3 -------- */
__global__ void __launch_bounds__(BDIM) pool_block_kernel(
    const float* __restrict__ w0, const float* __restrict__ b0,
    const float* __restrict__ w1, const float* __restrict__ b1,
    const float* __restrict__ ws, int srcA, int N)
{
    extern __shared__ float smem[];
    float* sW0 = smem;
    float* sWs = sW0 + 64*HID_;
    float* sW1 = sWs + 64*HID_;
    float* sB0 = sW1 + HID_*HID_;
    float* sB1 = sB0 + HID_;
    float* sx  = sB1 + HID_;

    for (int t = threadIdx.x; t < 64*HID_; t += BDIM) { sW0[t] = w0[t]; sWs[t] = ws[t]; }
    for (int t = threadIdx.x; t < HID_*HID_; t += BDIM) sW1[t] = w1[t];
    for (int t = threadIdx.x; t < HID_; t += BDIM) { sB0[t] = b0[t]; sB1[t] = b1[t]; }
    __syncthreads();

    int slot = blockIdx.x*BDIM + threadIdx.x;
    if (slot >= N) return;
    int tid = threadIdx.x;
    int gidx = g_sgidx[slot];

    const u32* cellSrc = srcA ? g_cellA : g_cellB;
    u32*       cellDst = srcA ? g_cellB : g_cellA;

    const float4* np = reinterpret_cast<const float4*>(&g_net[(size_t)slot*HID_]);
    const uint4*  pp = reinterpret_cast<const uint4*>(&cellSrc[gidx*HID_]);
#pragma unroll
    for (int j = 0; j < 8; j++) {
        float4 a = np[j];
        sx[(4*j+0)*BDIM + tid] = a.x; sx[(4*j+1)*BDIM + tid] = a.y;
        sx[(4*j+2)*BDIM + tid] = a.z; sx[(4*j+3)*BDIM + tid] = a.w;
        uint4 pb = pp[j];
        sx[(32+4*j+0)*BDIM + tid] = funmap(pb.x); sx[(32+4*j+1)*BDIM + tid] = funmap(pb.y);
        sx[(32+4*j+2)*BDIM + tid] = funmap(pb.z); sx[(32+4*j+3)*BDIM + tid] = funmap(pb.w);
    }

    float out[HID_];
    resblock_f32x2(sx, tid, sW0, sB0, sW1, sB1, sWs, out);

    float4* nw = reinterpret_cast<float4*>(&g_net[(size_t)slot*HID_]);
#pragma unroll
    for (int j = 0; j < 8; j++)
        nw[j] = make_float4(out[4*j], out[4*j+1], out[4*j+2], out[4*j+3]);

    scatter_max(cellDst, gidx, out);
}

/* -------- stage 4 -------- */
__global__ void __launch_bounds__(BDIM) final_kernel(
    const float* __restrict__ w0, const float* __restrict__ b0,
    const float* __restrict__ w1, const float* __restrict__ b1,
    const float* __restrict__ ws,
    const float* __restrict__ fcw, const float* __restrict__ fcb,
    int srcA, int N)
{
    extern __shared__ float smem[];
    float* sW0 = smem;
    float* sWs = sW0 + 64*HID_;
    float* sW1 = sWs + 64*HID_;
    float* sFc = sW1 + HID_*HID_;
    float* sB0 = sFc + HID_*HID_;
    float* sB1 = sB0 + HID_;
    float* sFb = sB1 + HID_;
    float* sx  = sFb + HID_;

    for (int t = threadIdx.x; t < 64*HID_; t += BDIM) { sW0[t] = w0[t]; sWs[t] = ws[t]; }
    for (int t = threadIdx.x; t < HID_*HID_; t += BDIM) { sW1[t] = w1[t]; sFc[t] = fcw[t]; }
    for (int t = threadIdx.x; t < HID_; t += BDIM) { sB0[t] = b0[t]; sB1[t] = b1[t]; sFb[t] = fcb[t]; }
    __syncthreads();

    int slot = blockIdx.x*BDIM + threadIdx.x;
    if (slot >= N) return;
    int tid = threadIdx.x;
    int gidx = g_sgidx[slot];

    const u32* cellSrc = srcA ? g_cellA : g_cellB;

    const float4* np = reinterpret_cast<const float4*>(&g_net[(size_t)slot*HID_]);
    const uint4*  pp = reinterpret_cast<const uint4*>(&cellSrc[gidx*HID_]);
#pragma unroll
    for (int j = 0; j < 8; j++) {
        float4 a = np[j];
        sx[(4*j+0)*BDIM + tid] = a.x; sx[(4*j+1)*BDIM + tid] = a.y;
        sx[(4*j+2)*BDIM + tid] = a.z; sx[(4*j+3)*BDIM + tid] = a.w;
        uint4 pb = pp[j];
        sx[(32+4*j+0)*BDIM + tid] = funmap(pb.x); sx[(32+4*j+1)*BDIM + tid] = funmap(pb.y);
        sx[(32+4*j+2)*BDIM + tid] = funmap(pb.z); sx[(32+4*j+3)*BDIM + tid] = funmap(pb.w);
    }

    float out[HID_];
    resblock_f32x2(sx, tid, sW0, sB0, sW1, sB1, sWs, out);

    u64 c2[16];
    const u64* fb2 = reinterpret_cast<const u64*>(sFb);
#pragma unroll
    for (int j = 0; j < 16; j++) c2[j] = fb2[j];
#pragma unroll
    for (int k = 0; k < HID_; k++) {
        u64 ok2 = splat2(out[k]);
        const ulonglong2* r = reinterpret_cast<const ulonglong2*>(sFc + k*HID_);
#pragma unroll
        for (int j = 0; j < 8; j++) {
            ulonglong2 a = r[j];
            ffma2(c2[2*j+0], ok2, a.x); ffma2(c2[2*j+1], ok2, a.y);
        }
    }
    float* sp = &g_sums[gidx*HID_];
#pragma unroll
    for (int j = 0; j < 16; j++) {
        float lo, hi; unpack2(c2[j], lo, hi);
        atomicAdd(sp + 2*j + 0, lo);
        atomicAdd(sp + 2*j + 1, hi);
    }
}

/* -------- output -------- */
__global__ void output_kernel(float* __restrict__ out, int total) {
    int t = blockIdx.x*blockDim.x + threadIdx.x;
    if (t >= total) return;
    int g = t & (G_ - 1);
    int c = (t >> 15) & (HID_ - 1);
    int b = t >> 20;
    int bg = b*G_ + g;
    float cnt = fmaxf((float)g_hist[bg], 1.0f);
    out[t] = g_sums[bg*HID_ + c] / cnt;
}

/* -------- host -------- */
extern "C" void kernel_launch(void* const* d_in, const int* in_sizes, int n_in,
                              void* d_out, int out_size) {
    const float* p   = (const float*)d_in[0];
    const float* Wp  = (const float*)d_in[1];
    const float* Bp  = (const float*)d_in[2];
    const float* W0  = (const float*)d_in[3];
    const float* B0  = (const float*)d_in[4];
    const float* W1  = (const float*)d_in[5];
    const float* B1  = (const float*)d_in[6];
    const float* Ws  = (const float*)d_in[7];
    const float* Fc  = (const float*)d_in[8];
    const float* FcB = (const float*)d_in[9];
    float* out = (float*)d_out;

    int T = in_sizes[0] / (B_ * 3);
    int N = B_ * T;
    int nb = (N + BDIM - 1) / BDIM;

    const int P0_SMEM = (3840 + 2048 + 2048 + 1024 + 64 + 32 + 32 + 64*BDIM) * 4;
    const int PB_SMEM = (2048 + 2048 + 1024 + 32 + 32 + 64*BDIM) * 4;
    const int PF_SMEM = (2048 + 2048 + 1024 + 1024 + 32 + 32 + 32 + 64*BDIM) * 4;

    cudaFuncSetAttribute(point0_kernel, cudaFuncAttributeMaxDynamicSharedMemorySize, P0_SMEM);
    cudaFuncSetAttribute(pool_block_kernel, cudaFuncAttributeMaxDynamicSharedMemorySize, PB_SMEM);
    cudaFuncSetAttribute(final_kernel, cudaFuncAttributeMaxDynamicSharedMemorySize, PF_SMEM);

    /* sort pre-pass */
    zero_hist_kernel<<<64, 256>>>();
    index_hist_kernel<<<nb, BDIM>>>(p, T, N);
    scan_kernel<<<1, 1024>>>();
    perm_kernel<<<nb, BDIM>>>(N);

    init_cells_kernel<<<512, 256>>>(0);
    point0_kernel<<<nb, BDIM, P0_SMEM>>>(p, Wp, Bp, W0, B0, W1, B1, Ws, N);

    init_cells_kernel<<<512, 256>>>(1);
    pool_block_kernel<<<nb, BDIM, PB_SMEM>>>(W0 + 1*64*HID_, B0 + 1*HID_,
                                             W1 + 1*HID_*HID_, B1 + 1*HID_,
                                             Ws + 1*64*HID_, 1, N);
    init_cells_kernel<<<512, 256>>>(0);
    pool_block_kernel<<<nb, BDIM, PB_SMEM>>>(W0 + 2*64*HID_, B0 + 2*HID_,
                                             W1 + 2*HID_*HID_, B1 + 2*HID_,
                                             Ws + 2*64*HID_, 0, N);
    init_cells_kernel<<<512, 256>>>(1);
    pool_block_kernel<<<nb, BDIM, PB_SMEM>>>(W0 + 3*64*HID_, B0 + 3*HID_,
                                             W1 + 3*HID_*HID_, B1 + 3*HID_,
                                             Ws + 3*64*HID_, 1, N);
    clear_sums_kernel<<<512, 256>>>();
    final_kernel<<<nb, BDIM, PF_SMEM>>>(W0 + 4*64*HID_, B0 + 4*HID_,
                                        W1 + 4*HID_*HID_, B1 + 4*HID_,
                                        Ws + 4*64*HID_, Fc, FcB, 0, N);

    output_kernel<<<(out_size + 255)/256, 256>>>(out, out_size);
}

// round 6
// speedup vs baseline: 1.2245x; 1.2245x over previous
#include <cuda_runtime.h>
#include <float.h>
#include <math.h>

#define B_     2
#define RESO_  32
#define G_     (RESO_*RESO_*RESO_)
#define BG_    (B_*G_)
#define HID_   32
#define NMAX_  524288
#define BDIM   128

typedef unsigned long long u64;

__device__ __forceinline__ u64 splat2(float v) {
    u64 r; asm("mov.b64 %0, {%1, %1};" : "=l"(r) : "f"(v)); return r;
}
__device__ __forceinline__ void unpack2(u64 v, float& lo, float& hi) {
    asm("mov.b64 {%0, %1}, %2;" : "=f"(lo), "=f"(hi) : "l"(v));
}
__device__ __forceinline__ void ffma2(u64& d, u64 a, u64 b) {
    asm("fma.rn.f32x2 %0, %1, %2, %0;" : "+l"(d) : "l"(a), "l"(b));
}

/* -------- scratch -------- */
__device__ float g_net[(size_t)NMAX_*HID_];   /* by slot; reused for c at the end */
__device__ float g_psort[(size_t)NMAX_*3];
__device__ int   g_gidx[NMAX_];
__device__ int   g_sgidx[NMAX_];
__device__ int   g_hist[BG_];
__device__ int   g_start[BG_];
__device__ int   g_cursor[BG_];
__device__ float g_cellA[BG_*HID_];
__device__ float g_cellB[BG_*HID_];

/* -------- sort pre-pass -------- */
__global__ void zero_hist_kernel() {
    int s = gridDim.x*blockDim.x;
    for (int i = blockIdx.x*blockDim.x + threadIdx.x; i < BG_; i += s) g_hist[i] = 0;
}
__global__ void index_hist_kernel(const float* __restrict__ p, int T, int N) {
    int i = blockIdx.x*blockDim.x + threadIdx.x;
    if (i >= N) return;
    float p0 = p[3*i+0], p1 = p[3*i+1], p2 = p[3*i+2];
    int b = i / T;
    float pn0 = fminf(fmaxf(__fdiv_rn(p0, 1.101f) + 0.5f, 0.0f), 0.999f);
    float pn1 = fminf(fmaxf(__fdiv_rn(p1, 1.101f) + 0.5f, 0.0f), 0.999f);
    float pn2 = fminf(fmaxf(__fdiv_rn(p2, 1.101f) + 0.5f, 0.0f), 0.999f);
    int gidx = (int)floorf(pn0*32.f) + RESO_*((int)floorf(pn1*32.f) + RESO_*(int)floorf(pn2*32.f)) + b*G_;
    g_gidx[i] = gidx;
    atomicAdd(&g_hist[gidx], 1);
}
__global__ void scan_kernel() {
    __shared__ int part[1024];
    int t = threadIdx.x, base = t*64, s = 0;
#pragma unroll
    for (int j = 0; j < 64; j++) s += g_hist[base+j];
    part[t] = s; __syncthreads();
    for (int off = 1; off < 1024; off <<= 1) {
        int v = (t >= off) ? part[t-off] : 0;
        __syncthreads(); part[t] += v; __syncthreads();
    }
    int run = (t == 0) ? 0 : part[t-1];
#pragma unroll
    for (int j = 0; j < 64; j++) {
        int c = g_hist[base+j];
        g_start[base+j] = run; g_cursor[base+j] = run;
        run += c;
    }
}
__global__ void perm_kernel(const float* __restrict__ p, int N) {
    int i = blockIdx.x*blockDim.x + threadIdx.x;
    if (i >= N) return;
    int gidx = g_gidx[i];
    int slot = atomicAdd(&g_cursor[gidx], 1);
    g_sgidx[slot] = gidx;
    g_psort[(size_t)slot*3+0] = p[3*i+0];
    g_psort[(size_t)slot*3+1] = p[3*i+1];
    g_psort[(size_t)slot*3+2] = p[3*i+2];
}

/* -------- cell-parallel max-pool: g_net (CSR) -> cell (no atomics) -------- */
__global__ void maxpool_kernel(float* __restrict__ dst) {
    int t = blockIdx.x*blockDim.x + threadIdx.x;
    if (t >= BG_*8) return;
    int cell = t >> 3, q = (t & 7) * 4;
    int s = g_start[cell], n = g_hist[cell];
    float4 m = make_float4(0.f, 0.f, 0.f, 0.f);
    if (n > 0) {
        m = *reinterpret_cast<const float4*>(&g_net[(size_t)s*HID_ + q]);
        for (int k = 1; k < n; k++) {
            float4 v = *reinterpret_cast<const float4*>(&g_net[(size_t)(s+k)*HID_ + q]);
            m.x = fmaxf(m.x, v.x); m.y = fmaxf(m.y, v.y);
            m.z = fmaxf(m.z, v.z); m.w = fmaxf(m.w, v.w);
        }
    }
    *reinterpret_cast<float4*>(&dst[cell*HID_ + q]) = m;
}

/* -------- residual block (packed f32x2) -------- */
__device__ __forceinline__ void resblock_f32x2(
    const float* sx, int tid,
    const float* __restrict__ sW0, const float* __restrict__ sB0,
    const float* __restrict__ sW1, const float* __restrict__ sB1,
    const float* __restrict__ sWs, float* out)
{
    u64 h2[16], o2[16];
    const u64* b0p = reinterpret_cast<const u64*>(sB0);
    const u64* b1p = reinterpret_cast<const u64*>(sB1);
#pragma unroll
    for (int j = 0; j < 16; j++) { h2[j] = b0p[j]; o2[j] = b1p[j]; }
#pragma unroll 4
    for (int k = 0; k < 64; k++) {
        float xk = sx[k*BDIM + tid];
        u64 xk2 = splat2(xk);
        u64 xr2 = splat2(fmaxf(xk, 0.0f));
        const ulonglong2* r0 = reinterpret_cast<const ulonglong2*>(sW0 + k*HID_);
        const ulonglong2* rs = reinterpret_cast<const ulonglong2*>(sWs + k*HID_);
#pragma unroll
        for (int j = 0; j < 8; j++) {
            ulonglong2 a = r0[j], s = rs[j];
            ffma2(h2[2*j+0], xr2, a.x); ffma2(h2[2*j+1], xr2, a.y);
            ffma2(o2[2*j+0], xk2, s.x); ffma2(o2[2*j+1], xk2, s.y);
        }
    }
    float hr[HID_];
#pragma unroll
    for (int j = 0; j < 16; j++) {
        float lo, hi; unpack2(h2[j], lo, hi);
        hr[2*j+0] = fmaxf(lo, 0.0f); hr[2*j+1] = fmaxf(hi, 0.0f);
    }
#pragma unroll
    for (int k = 0; k < HID_; k++) {
        u64 hk2 = splat2(hr[k]);
        const ulonglong2* r1 = reinterpret_cast<const ulonglong2*>(sW1 + k*HID_);
#pragma unroll
        for (int j = 0; j < 8; j++) {
            ulonglong2 a = r1[j];
            ffma2(o2[2*j+0], hk2, a.x); ffma2(o2[2*j+1], hk2, a.y);
        }
    }
#pragma unroll
    for (int j = 0; j < 16; j++) unpack2(o2[j], out[2*j], out[2*j+1]);
}

/* -------- stage 0 -------- */
__global__ void __launch_bounds__(BDIM) point0_kernel(
    const float* __restrict__ Wp, const float* __restrict__ Bp,
    const float* __restrict__ w0, const float* __restrict__ b0,
    const float* __restrict__ w1, const float* __restrict__ b1,
    const float* __restrict__ ws, int N)
{
    extern __shared__ float smem[];
    float* sWp = smem;
    float* sW0 = sWp + 60*64;
    float* sWs = sW0 + 64*HID_;
    float* sW1 = sWs + 64*HID_;
    float* sBp = sW1 + HID_*HID_;
    float* sB0 = sBp + 64;
    float* sB1 = sB0 + HID_;
    float* sx  = sB1 + HID_;

    for (int t = threadIdx.x; t < 60*64; t += BDIM) sWp[t] = Wp[t];
    for (int t = threadIdx.x; t < 64*HID_; t += BDIM) { sW0[t] = w0[t]; sWs[t] = ws[t]; }
    for (int t = threadIdx.x; t < HID_*HID_; t += BDIM) sW1[t] = w1[t];
    for (int t = threadIdx.x; t < 64; t += BDIM) sBp[t] = Bp[t];
    for (int t = threadIdx.x; t < HID_; t += BDIM) { sB0[t] = b0[t]; sB1[t] = b1[t]; }
    __syncthreads();

    int slot = blockIdx.x*BDIM + threadIdx.x;
    if (slot >= N) return;
    int tid = threadIdx.x;

    float p0 = g_psort[(size_t)slot*3+0];
    float p1 = g_psort[(size_t)slot*3+1];
    float p2 = g_psort[(size_t)slot*3+2];

    u64 x2[32];
    const u64* bp2 = reinterpret_cast<const u64*>(sBp);
#pragma unroll
    for (int j = 0; j < 32; j++) x2[j] = bp2[j];

    float q[3] = {2.0f*p0 - 1.0f, 2.0f*p1 - 1.0f, 2.0f*p2 - 1.0f};
#pragma unroll
    for (int d = 0; d < 3; d++) {
        float y = q[d];
#pragma unroll 1
        for (int l = 0; l < 10; l++) {
            float s, c;
            sincospif(y, &s, &c);
            u64 s2 = splat2(s), c2 = splat2(c);
            const ulonglong2* rs_ = reinterpret_cast<const ulonglong2*>(sWp + (l*6 + d)*64);
            const ulonglong2* rc_ = reinterpret_cast<const ulonglong2*>(sWp + (l*6 + 3 + d)*64);
#pragma unroll
            for (int j = 0; j < 16; j++) {
                ulonglong2 a = rs_[j], bb = rc_[j];
                ffma2(x2[2*j+0], s2, a.x); ffma2(x2[2*j+1], s2, a.y);
                ffma2(x2[2*j+0], c2, bb.x); ffma2(x2[2*j+1], c2, bb.y);
            }
            y *= 2.0f;
        }
    }
#pragma unroll
    for (int j = 0; j < 32; j++) {
        float lo, hi; unpack2(x2[j], lo, hi);
        sx[(2*j+0)*BDIM + tid] = lo;
        sx[(2*j+1)*BDIM + tid] = hi;
    }

    float out[HID_];
    resblock_f32x2(sx, tid, sW0, sB0, sW1, sB1, sWs, out);

    float4* nw = reinterpret_cast<float4*>(&g_net[(size_t)slot*HID_]);
#pragma unroll
    for (int j = 0; j < 8; j++)
        nw[j] = make_float4(out[4*j], out[4*j+1], out[4*j+2], out[4*j+3]);
}

/* -------- stages 1..3 -------- */
__global__ void __launch_bounds__(BDIM) pool_block_kernel(
    const float* __restrict__ w0, const float* __restrict__ b0,
    const float* __restrict__ w1, const float* __restrict__ b1,
    const float* __restrict__ ws, const float* __restrict__ cellSrc, int N)
{
    extern __shared__ float smem[];
    float* sW0 = smem;
    float* sWs = sW0 + 64*HID_;
    float* sW1 = sWs + 64*HID_;
    float* sB0 = sW1 + HID_*HID_;
    float* sB1 = sB0 + HID_;
    float* sx  = sB1 + HID_;

    for (int t = threadIdx.x; t < 64*HID_; t += BDIM) { sW0[t] = w0[t]; sWs[t] = ws[t]; }
    for (int t = threadIdx.x; t < HID_*HID_; t += BDIM) sW1[t] = w1[t];
    for (int t = threadIdx.x; t < HID_; t += BDIM) { sB0[t] = b0[t]; sB1[t] = b1[t]; }
    __syncthreads();

    int slot = blockIdx.x*BDIM + threadIdx.x;
    if (slot >= N) return;
    int tid = threadIdx.x;
    int gidx = g_sgidx[slot];

    const float4* np = reinterpret_cast<const float4*>(&g_net[(size_t)slot*HID_]);
    const float4* pp = reinterpret_cast<const float4*>(&cellSrc[gidx*HID_]);
#pragma unroll
    for (int j = 0; j < 8; j++) {
        float4 a = np[j];
        sx[(4*j+0)*BDIM + tid] = a.x; sx[(4*j+1)*BDIM + tid] = a.y;
        sx[(4*j+2)*BDIM + tid] = a.z; sx[(4*j+3)*BDIM + tid] = a.w;
        float4 pb = pp[j];
        sx[(32+4*j+0)*BDIM + tid] = pb.x; sx[(32+4*j+1)*BDIM + tid] = pb.y;
        sx[(32+4*j+2)*BDIM + tid] = pb.z; sx[(32+4*j+3)*BDIM + tid] = pb.w;
    }

    float out[HID_];
    resblock_f32x2(sx, tid, sW0, sB0, sW1, sB1, sWs, out);

    float4* nw = reinterpret_cast<float4*>(&g_net[(size_t)slot*HID_]);
#pragma unroll
    for (int j = 0; j < 8; j++)
        nw[j] = make_float4(out[4*j], out[4*j+1], out[4*j+2], out[4*j+3]);
}

/* -------- stage 4: resblock4 + fc_c, store c by slot -------- */
__global__ void __launch_bounds__(BDIM) final_kernel(
    const float* __restrict__ w0, const float* __restrict__ b0,
    const float* __restrict__ w1, const float* __restrict__ b1,
    const float* __restrict__ ws,
    const float* __restrict__ fcw, const float* __restrict__ fcb,
    const float* __restrict__ cellSrc, int N)
{
    extern __shared__ float smem[];
    float* sW0 = smem;
    float* sWs = sW0 + 64*HID_;
    float* sW1 = sWs + 64*HID_;
    float* sFc = sW1 + HID_*HID_;
    float* sB0 = sFc + HID_*HID_;
    float* sB1 = sB0 + HID_;
    float* sFb = sB1 + HID_;
    float* sx  = sFb + HID_;

    for (int t = threadIdx.x; t < 64*HID_; t += BDIM) { sW0[t] = w0[t]; sWs[t] = ws[t]; }
    for (int t = threadIdx.x; t < HID_*HID_; t += BDIM) { sW1[t] = w1[t]; sFc[t] = fcw[t]; }
    for (int t = threadIdx.x; t < HID_; t += BDIM) { sB0[t] = b0[t]; sB1[t] = b1[t]; sFb[t] = fcb[t]; }
    __syncthreads();

    int slot = blockIdx.x*BDIM + threadIdx.x;
    if (slot >= N) return;
    int tid = threadIdx.x;
    int gidx = g_sgidx[slot];

    const float4* np = reinterpret_cast<const float4*>(&g_net[(size_t)slot*HID_]);
    const float4* pp = reinterpret_cast<const float4*>(&cellSrc[gidx*HID_]);
#pragma unroll
    for (int j = 0; j < 8; j++) {
        float4 a = np[j];
        sx[(4*j+0)*BDIM + tid] = a.x; sx[(4*j+1)*BDIM + tid] = a.y;
        sx[(4*j+2)*BDIM + tid] = a.z; sx[(4*j+3)*BDIM + tid] = a.w;
        float4 pb = pp[j];
        sx[(32+4*j+0)*BDIM + tid] = pb.x; sx[(32+4*j+1)*BDIM + tid] = pb.y;
        sx[(32+4*j+2)*BDIM + tid] = pb.z; sx[(32+4*j+3)*BDIM + tid] = pb.w;
    }

    float out[HID_];
    resblock_f32x2(sx, tid, sW0, sB0, sW1, sB1, sWs, out);

    u64 c2[16];
    const u64* fb2 = reinterpret_cast<const u64*>(sFb);
#pragma unroll
    for (int j = 0; j < 16; j++) c2[j] = fb2[j];
#pragma unroll
    for (int k = 0; k < HID_; k++) {
        u64 ok2 = splat2(out[k]);
        const ulonglong2* r = reinterpret_cast<const ulonglong2*>(sFc + k*HID_);
#pragma unroll
        for (int j = 0; j < 8; j++) {
            ulonglong2 a = r[j];
            ffma2(c2[2*j+0], ok2, a.x); ffma2(c2[2*j+1], ok2, a.y);
        }
    }
    /* store c by slot (reuse g_net) */
    float4* cw = reinterpret_cast<float4*>(&g_net[(size_t)slot*HID_]);
#pragma unroll
    for (int j = 0; j < 8; j++) {
        float l0, h0, l1, h1;
        unpack2(c2[2*j], l0, h0); unpack2(c2[2*j+1], l1, h1);
        cw[j] = make_float4(l0, h0, l1, h1);
    }
}

/* -------- output: CSR mean + transpose to [B, CDIM, G] -------- */
__global__ void output_kernel(float* __restrict__ out, int total) {
    int t = blockIdx.x*blockDim.x + threadIdx.x;
    if (t >= total) return;
    int bg = t >> 5, ch = t & 31;
    int s = g_start[bg], n = g_hist[bg];
    float sum = 0.0f;
    for (int k = 0; k < n; k++) sum += g_net[(size_t)(s+k)*HID_ + ch];
    float mean = sum / fmaxf((float)n, 1.0f);
    int b = bg >> 15, g = bg & (G_ - 1);
    out[((size_t)b*HID_ + ch)*G_ + g] = mean;
}

/* -------- host -------- */
extern "C" void kernel_launch(void* const* d_in, const int* in_sizes, int n_in,
                              void* d_out, int out_size) {
    const float* p   = (const float*)d_in[0];
    const float* Wp  = (const float*)d_in[1];
    const float* Bp  = (const float*)d_in[2];
    const float* W0  = (const float*)d_in[3];
    const float* B0  = (const float*)d_in[4];
    const float* W1  = (const float*)d_in[5];
    const float* B1  = (const float*)d_in[6];
    const float* Ws  = (const float*)d_in[7];
    const float* Fc  = (const float*)d_in[8];
    const float* FcB = (const float*)d_in[9];
    float* out = (float*)d_out;

    int T = in_sizes[0] / (B_ * 3);
    int N = B_ * T;
    int nb = (N + BDIM - 1) / BDIM;

    const int P0_SMEM = (3840 + 2048 + 2048 + 1024 + 64 + 32 + 32 + 64*BDIM) * 4;
    const int PB_SMEM = (2048 + 2048 + 1024 + 32 + 32 + 64*BDIM) * 4;
    const int PF_SMEM = (2048 + 2048 + 1024 + 1024 + 32 + 32 + 32 + 64*BDIM) * 4;

    cudaFuncSetAttribute(point0_kernel, cudaFuncAttributeMaxDynamicSharedMemorySize, P0_SMEM);
    cudaFuncSetAttribute(pool_block_kernel, cudaFuncAttributeMaxDynamicSharedMemorySize, PB_SMEM);
    cudaFuncSetAttribute(final_kernel, cudaFuncAttributeMaxDynamicSharedMemorySize, PF_SMEM);

    float* cellA; cudaGetSymbolAddress((void**)&cellA, g_cellA);
    float* cellB; cudaGetSymbolAddress((void**)&cellB, g_cellB);

    zero_hist_kernel<<<64, 256>>>();
    index_hist_kernel<<<nb, BDIM>>>(p, T, N);
    scan_kernel<<<1, 1024>>>();
    perm_kernel<<<nb, BDIM>>>(p, N);

    point0_kernel<<<nb, BDIM, P0_SMEM>>>(Wp, Bp, W0, B0, W1, B1, Ws, N);
    maxpool_kernel<<<BG_*8/256, 256>>>(cellA);

    pool_block_kernel<<<nb, BDIM, PB_SMEM>>>(W0 + 1*64*HID_, B0 + 1*HID_,
        W1 + 1*HID_*HID_, B1 + 1*HID_, Ws + 1*64*HID_, cellA, N);
    maxpool_kernel<<<BG_*8/256, 256>>>(cellB);

    pool_block_kernel<<<nb, BDIM, PB_SMEM>>>(W0 + 2*64*HID_, B0 + 2*HID_,
        W1 + 2*HID_*HID_, B1 + 2*HID_, Ws + 2*64*HID_, cellB, N);
    maxpool_kernel<<<BG_*8/256, 256>>>(cellA);

    pool_block_kernel<<<nb, BDIM, PB_SMEM>>>(W0 + 3*64*HID_, B0 + 3*HID_,
        W1 + 3*HID_*HID_, B1 + 3*HID_, Ws + 3*64*HID_, cellA, N);
    maxpool_kernel<<<BG_*8/256, 256>>>(cellB);

    final_kernel<<<nb, BDIM, PF_SMEM>>>(W0 + 4*64*HID_, B0 + 4*HID_,
        W1 + 4*HID_*HID_, B1 + 4*HID_, Ws + 4*64*HID_, Fc, FcB, cellB, N);

    output_kernel<<<(out_size + 255)/256, 256>>>(out, out_size);
}

// round 8
// speedup vs baseline: 1.3148x; 1.0737x over previous
#include <cuda_runtime.h>
#include <cuda_bf16.h>
#include <math.h>
#include <stdint.h>

#define B_ 2
#define RESO_ 32
#define G_ 32768
#define BG_ 65536
#define HID_ 32
#define NMAX_ 524288
#define BDIM 128
#define APAD 400        /* A row stride bytes (200 bf16) */
#define BP32 80         /* B row stride, N=32 */
#define BP64 144        /* B row stride, N=64 */

/* smem offsets: A tile 128*400 = 51200 */
#define O_A   0
#define O_W0  51200
#define O_WS  66560
#define O_W1  81920
#define O_SB0 89600
#define O_SB1 89728
#define SM_POOL 89856
#define O_FC  89856
#define O_SFB 97536
#define SM_FIN 97664
#define O_WP  51200     /* point0: Wp stack 192*144=27648 */
#define P_W0  78848
#define P_WS  94208
#define P_W1  109568
#define P_SB0 117248
#define P_SB1 117376
#define P_SBP 117504
#define SM_P0 117760

/* -------- scratch -------- */
__device__ float g_net[(size_t)NMAX_*HID_];
__device__ float g_psort[(size_t)NMAX_*3];
__device__ int   g_gidx[NMAX_];
__device__ int   g_sgidx[NMAX_];
__device__ int   g_hist[BG_];
__device__ int   g_start[BG_];
__device__ int   g_cursor[BG_];
__device__ float g_cellA[BG_*HID_];
__device__ float g_cellB[BG_*HID_];

/* -------- helpers -------- */
__device__ __forceinline__ uint32_t smem_u32(const void* p) {
    uint32_t a;
    asm("{ .reg .u64 t; cvta.to.shared.u64 t, %1; cvt.u32.u64 %0, t; }" : "=r"(a) : "l"(p));
    return a;
}
__device__ __forceinline__ void ldmA(uint32_t a[4], uint32_t addr) {
    asm volatile("ldmatrix.sync.aligned.m8n8.x4.shared.b16 {%0,%1,%2,%3}, [%4];"
        : "=r"(a[0]), "=r"(a[1]), "=r"(a[2]), "=r"(a[3]) : "r"(addr));
}
__device__ __forceinline__ void ldmB(uint32_t b[2], uint32_t addr) {
    asm volatile("ldmatrix.sync.aligned.m8n8.x2.trans.shared.b16 {%0,%1}, [%2];"
        : "=r"(b[0]), "=r"(b[1]) : "r"(addr));
}
__device__ __forceinline__ void mma16816(float d[4], const uint32_t a[4], const uint32_t b[2]) {
    asm volatile("mma.sync.aligned.m16n8k16.row.col.f32.bf16.bf16.f32 "
        "{%0,%1,%2,%3},{%4,%5,%6,%7},{%8,%9},{%0,%1,%2,%3};"
        : "+f"(d[0]), "+f"(d[1]), "+f"(d[2]), "+f"(d[3])
        : "r"(a[0]), "r"(a[1]), "r"(a[2]), "r"(a[3]), "r"(b[0]), "r"(b[1]));
}
__device__ __forceinline__ void hm(float a, float b, uint32_t& H, uint32_t& M) {
    __nv_bfloat16 h0 = __float2bfloat16(a), h1 = __float2bfloat16(b);
    uint16_t u0 = *reinterpret_cast<uint16_t*>(&h0), u1 = *reinterpret_cast<uint16_t*>(&h1);
    H = ((uint32_t)u1 << 16) | u0;
    __nv_bfloat162 m = __floats2bfloat162_rn(a - __bfloat162float(h0), b - __bfloat162float(h1));
    M = *reinterpret_cast<uint32_t*>(&m);
}
/* per-thread row v[64] -> A stack [hi|mid|hi], conflict-free uint4 stores */
__device__ __forceinline__ void writeRow64(char* A, int row, const float* v, bool dorelu) {
    char* base = A + row*APAD;
#pragma unroll
    for (int g = 0; g < 8; g++) {
        uint32_t H[4], M[4];
#pragma unroll
        for (int j = 0; j < 4; j++) {
            float a = v[8*g+2*j], b = v[8*g+2*j+1];
            if (dorelu) { a = fmaxf(a, 0.f); b = fmaxf(b, 0.f); }
            hm(a, b, H[j], M[j]);
        }
        *(uint4*)(base + g*16)       = make_uint4(H[0], H[1], H[2], H[3]);
        *(uint4*)(base + 128 + g*16) = make_uint4(M[0], M[1], M[2], M[3]);
        *(uint4*)(base + 256 + g*16) = make_uint4(H[0], H[1], H[2], H[3]);
    }
}
/* D fragments (+bias, opt relu) -> A stack of K = NT*8 */
template<int NT>
__device__ __forceinline__ void fragToA(char* A, int wid, int lane,
                                        float acc[2][NT][4], const float* bias, bool dorelu) {
    const int K2 = NT*16, K4 = NT*32;
    int r0 = wid*32 + (lane >> 2);
    int cb = (lane & 3)*2;
#pragma unroll
    for (int mt = 0; mt < 2; mt++)
#pragma unroll
    for (int half = 0; half < 2; half++) {
        char* base = A + (r0 + mt*16 + half*8)*APAD;
#pragma unroll
        for (int nt = 0; nt < NT; nt++) {
            int c = nt*8 + cb;
            float v0 = acc[mt][nt][half*2+0] + bias[c];
            float v1 = acc[mt][nt][half*2+1] + bias[c+1];
            if (dorelu) { v0 = fmaxf(v0, 0.f); v1 = fmaxf(v1, 0.f); }
            uint32_t H, M; hm(v0, v1, H, M);
            *(uint32_t*)(base + c*2)      = H;
            *(uint32_t*)(base + K2 + c*2) = M;
            *(uint32_t*)(base + K4 + c*2) = H;
        }
    }
}
__device__ __forceinline__ void fragStore(int ctaBase, int N, int wid, int lane,
                                          float acc[2][4][4], const float* bias) {
    int r0 = wid*32 + (lane >> 2);
    int cb = (lane & 3)*2;
#pragma unroll
    for (int mt = 0; mt < 2; mt++)
#pragma unroll
    for (int half = 0; half < 2; half++) {
        int slot = ctaBase + r0 + mt*16 + half*8;
        if (slot < N) {
            float* g = &g_net[(size_t)slot*HID_];
#pragma unroll
            for (int nt = 0; nt < 4; nt++) {
                int c = nt*8 + cb;
                *(float2*)(g + c) = make_float2(acc[mt][nt][half*2] + bias[c],
                                                acc[mt][nt][half*2+1] + bias[c+1]);
            }
        }
    }
}
template<int KT, int NT>
__device__ __forceinline__ void warp_gemm(uint32_t aU, uint32_t bU, int bpad,
                                          int wid, int lane, float acc[2][NT][4]) {
    uint32_t aAddr = aU + (uint32_t)(wid*32 + (lane & 15))*APAD + (uint32_t)((lane & 16) ? 16 : 0);
    uint32_t bRow = (uint32_t)(lane & 15);
#pragma unroll
    for (int kt = 0; kt < KT; kt++) {
        uint32_t a0[4], a1[4];
        ldmA(a0, aAddr + kt*32);
        ldmA(a1, aAddr + kt*32 + 16*APAD);
#pragma unroll
        for (int nt = 0; nt < NT; nt++) {
            uint32_t b[2];
            ldmB(b, bU + (kt*16 + bRow)*bpad + nt*16);
            mma16816(acc[0][nt], a0, b);
            mma16816(acc[1][nt], a1, b);
        }
    }
}
/* weights gmem [K][N] -> stacked [Bh;Bh;Bm], rows spaced Kpad */
__device__ void prepB(char* dst, int tid, const float* __restrict__ g,
                      int K, int Kpad, int N, int bpad) {
    for (int t = tid; t < K*N; t += BDIM) {
        int k = t / N, n = t - k*N;
        float w = g[t];
        __nv_bfloat16 h = __float2bfloat16(w);
        __nv_bfloat16 m = __float2bfloat16(w - __bfloat162float(h));
        *(__nv_bfloat16*)(dst + k*bpad + n*2) = h;
        *(__nv_bfloat16*)(dst + (Kpad+k)*bpad + n*2) = h;
        *(__nv_bfloat16*)(dst + (2*Kpad+k)*bpad + n*2) = m;
    }
}

/* -------- sort pre-pass + pooling -------- */
__global__ void zero_hist_kernel() {
    int s = gridDim.x*blockDim.x;
    for (int i = blockIdx.x*blockDim.x + threadIdx.x; i < BG_; i += s) g_hist[i] = 0;
}
__global__ void index_hist_kernel(const float* __restrict__ p, int T, int N) {
    int i = blockIdx.x*blockDim.x + threadIdx.x;
    if (i >= N) return;
    float p0 = p[3*i+0], p1 = p[3*i+1], p2 = p[3*i+2];
    int b = i / T;
    float pn0 = fminf(fmaxf(__fdiv_rn(p0, 1.101f) + 0.5f, 0.0f), 0.999f);
    float pn1 = fminf(fmaxf(__fdiv_rn(p1, 1.101f) + 0.5f, 0.0f), 0.999f);
    float pn2 = fminf(fmaxf(__fdiv_rn(p2, 1.101f) + 0.5f, 0.0f), 0.999f);
    int gidx = (int)floorf(pn0*32.f) + RESO_*((int)floorf(pn1*32.f) + RESO_*(int)floorf(pn2*32.f)) + b*G_;
    g_gidx[i] = gidx;
    atomicAdd(&g_hist[gidx], 1);
}
__global__ void scan_kernel() {
    __shared__ int part[1024];
    int t = threadIdx.x, base = t*64, s = 0;
#pragma unroll
    for (int j = 0; j < 64; j++) s += g_hist[base+j];
    part[t] = s; __syncthreads();
    for (int off = 1; off < 1024; off <<= 1) {
        int v = (t >= off) ? part[t-off] : 0;
        __syncthreads(); part[t] += v; __syncthreads();
    }
    int run = (t == 0) ? 0 : part[t-1];
#pragma unroll
    for (int j = 0; j < 64; j++) {
        int c = g_hist[base+j];
        g_start[base+j] = run; g_cursor[base+j] = run; run += c;
    }
}
__global__ void perm_kernel(const float* __restrict__ p, int N) {
    int i = blockIdx.x*blockDim.x + threadIdx.x;
    if (i >= N) return;
    int gidx = g_gidx[i];
    int slot = atomicAdd(&g_cursor[gidx], 1);
    g_sgidx[slot] = gidx;
    g_psort[(size_t)slot*3+0] = p[3*i+0];
    g_psort[(size_t)slot*3+1] = p[3*i+1];
    g_psort[(size_t)slot*3+2] = p[3*i+2];
}
__global__ void maxpool_kernel(float* __restrict__ dst) {
    int t = blockIdx.x*blockDim.x + threadIdx.x;
    if (t >= BG_*8) return;
    int cell = t >> 3, q = (t & 7) * 4;
    int s = g_start[cell], n = g_hist[cell];
    float4 m = make_float4(0.f, 0.f, 0.f, 0.f);
    if (n > 0) {
        m = *reinterpret_cast<const float4*>(&g_net[(size_t)s*HID_ + q]);
        for (int k = 1; k < n; k++) {
            float4 v = *reinterpret_cast<const float4*>(&g_net[(size_t)(s+k)*HID_ + q]);
            m.x = fmaxf(m.x, v.x); m.y = fmaxf(m.y, v.y);
            m.z = fmaxf(m.z, v.z); m.w = fmaxf(m.w, v.w);
        }
    }
    *reinterpret_cast<float4*>(&dst[cell*HID_ + q]) = m;
}

/* -------- stage 0 -------- */
__global__ void __launch_bounds__(BDIM) point0_kernel(
    const float* __restrict__ Wp, const float* __restrict__ Bp,
    const float* __restrict__ w0, const float* __restrict__ b0g,
    const float* __restrict__ w1, const float* __restrict__ b1g,
    const float* __restrict__ ws, int N)
{
    extern __shared__ __align__(16) char sm[];
    uint32_t su = smem_u32(sm);
    int tid = threadIdx.x, wid = tid >> 5, lane = tid & 31;
    for (int t = tid; t < 27648/4; t += BDIM) ((uint32_t*)(sm + O_WP))[t] = 0;
    __syncthreads();
    prepB(sm+O_WP, tid, Wp, 60, 64, 64, BP64);
    prepB(sm+P_W0, tid, w0, 64, 64, 32, BP32);
    prepB(sm+P_WS, tid, ws, 64, 64, 32, BP32);
    prepB(sm+P_W1, tid, w1, 32, 32, 32, BP32);
    if (tid < 32) { ((float*)(sm+P_SB0))[tid] = b0g[tid]; ((float*)(sm+P_SB1))[tid] = b1g[tid]; }
    if (tid < 64) ((float*)(sm+P_SBP))[tid] = Bp[tid];
    __syncthreads();
    const float* b0 = (const float*)(sm+P_SB0);
    const float* b1 = (const float*)(sm+P_SB1);
    const float* sbp = (const float*)(sm+P_SBP);

    int ctaBase = blockIdx.x*BDIM;
    int slot = ctaBase + tid;
    float p0 = 0.f, p1 = 0.f, p2 = 0.f;
    if (slot < N) { p0 = g_psort[(size_t)slot*3]; p1 = g_psort[(size_t)slot*3+1]; p2 = g_psort[(size_t)slot*3+2]; }
    float pe[64];
#pragma unroll
    for (int j = 60; j < 64; j++) pe[j] = 0.f;
    float q[3] = {2.f*p0-1.f, 2.f*p1-1.f, 2.f*p2-1.f};
#pragma unroll
    for (int d = 0; d < 3; d++) {
        float y = q[d];
#pragma unroll 1
        for (int l = 0; l < 10; l++) {
            float s, c; sincospif(y, &s, &c);
            pe[l*6+d] = s; pe[l*6+3+d] = c;
            y *= 2.f;
        }
    }
    writeRow64(sm+O_A, tid, pe, false);
    __syncwarp();
    float accX[2][8][4] = {};
    warp_gemm<12,8>(su+O_A, su+O_WP, BP64, wid, lane, accX);
    __syncwarp();
    fragToA<8>(sm+O_A, wid, lane, accX, sbp, true);
    __syncwarp();
    float accH[2][4][4] = {};
    warp_gemm<12,4>(su+O_A, su+P_W0, BP32, wid, lane, accH);
    __syncwarp();
    fragToA<8>(sm+O_A, wid, lane, accX, sbp, false);
    __syncwarp();
    float accO[2][4][4] = {};
    warp_gemm<12,4>(su+O_A, su+P_WS, BP32, wid, lane, accO);
    __syncwarp();
    fragToA<4>(sm+O_A, wid, lane, accH, b0, true);
    __syncwarp();
    warp_gemm<6,4>(su+O_A, su+P_W1, BP32, wid, lane, accO);
    fragStore(ctaBase, N, wid, lane, accO, b1);
}

/* -------- stages 1..3 -------- */
__global__ void __launch_bounds__(BDIM) pool_block_kernel(
    const float* __restrict__ w0, const float* __restrict__ b0g,
    const float* __restrict__ w1, const float* __restrict__ b1g,
    const float* __restrict__ ws, const float* __restrict__ cellSrc, int N)
{
    extern __shared__ __align__(16) char sm[];
    uint32_t su = smem_u32(sm);
    int tid = threadIdx.x, wid = tid >> 5, lane = tid & 31;
    prepB(sm+O_W0, tid, w0, 64, 64, 32, BP32);
    prepB(sm+O_WS, tid, ws, 64, 64, 32, BP32);
    prepB(sm+O_W1, tid, w1, 32, 32, 32, BP32);
    if (tid < 32) { ((float*)(sm+O_SB0))[tid] = b0g[tid]; ((float*)(sm+O_SB1))[tid] = b1g[tid]; }
    __syncthreads();
    const float* b0 = (const float*)(sm+O_SB0);
    const float* b1 = (const float*)(sm+O_SB1);

    int ctaBase = blockIdx.x*BDIM;
    int slot = ctaBase + tid;
    float x[64];
    if (slot < N) {
        int gidx = g_sgidx[slot];
        const float4* np = (const float4*)&g_net[(size_t)slot*HID_];
        const float4* pp = (const float4*)&cellSrc[gidx*HID_];
#pragma unroll
        for (int j = 0; j < 8; j++) {
            float4 a = np[j]; x[4*j]=a.x; x[4*j+1]=a.y; x[4*j+2]=a.z; x[4*j+3]=a.w;
            float4 pb = pp[j]; x[32+4*j]=pb.x; x[32+4*j+1]=pb.y; x[32+4*j+2]=pb.z; x[32+4*j+3]=pb.w;
        }
    } else {
#pragma unroll
        for (int j = 0; j < 64; j++) x[j] = 0.f;
    }
    writeRow64(sm+O_A, tid, x, true);
    __syncwarp();
    float accH[2][4][4] = {};
    warp_gemm<12,4>(su+O_A, su+O_W0, BP32, wid, lane, accH);
    __syncwarp();
    writeRow64(sm+O_A, tid, x, false);
    __syncwarp();
    float accO[2][4][4] = {};
    warp_gemm<12,4>(su+O_A, su+O_WS, BP32, wid, lane, accO);
    __syncwarp();
    fragToA<4>(sm+O_A, wid, lane, accH, b0, true);
    __syncwarp();
    warp_gemm<6,4>(su+O_A, su+O_W1, BP32, wid, lane, accO);
    fragStore(ctaBase, N, wid, lane, accO, b1);
}

/* -------- stage 4 + fc_c -------- */
__global__ void __launch_bounds__(BDIM) final_kernel(
    const float* __restrict__ w0, const float* __restrict__ b0g,
    const float* __restrict__ w1, const float* __restrict__ b1g,
    const float* __restrict__ ws,
    const float* __restrict__ fcw, const float* __restrict__ fcb,
    const float* __restrict__ cellSrc, int N)
{
    extern __shared__ __align__(16) char sm[];
    uint32_t su = smem_u32(sm);
    int tid = threadIdx.x, wid = tid >> 5, lane = tid & 31;
    prepB(sm+O_W0, tid, w0, 64, 64, 32, BP32);
    prepB(sm+O_WS, tid, ws, 64, 64, 32, BP32);
    prepB(sm+O_W1, tid, w1, 32, 32, 32, BP32);
    prepB(sm+O_FC, tid, fcw, 32, 32, 32, BP32);
    if (tid < 32) {
        ((float*)(sm+O_SB0))[tid] = b0g[tid];
        ((float*)(sm+O_SB1))[tid] = b1g[tid];
        ((float*)(sm+O_SFB))[tid] = fcb[tid];
    }
    __syncthreads();
    const float* b0 = (const float*)(sm+O_SB0);
    const float* b1 = (const float*)(sm+O_SB1);
    const float* sfb = (const float*)(sm+O_SFB);

    int ctaBase = blockIdx.x*BDIM;
    int slot = ctaBase + tid;
    float x[64];
    if (slot < N) {
        int gidx = g_sgidx[slot];
        const float4* np = (const float4*)&g_net[(size_t)slot*HID_];
        const float4* pp = (const float4*)&cellSrc[gidx*HID_];
#pragma unroll
        for (int j = 0; j < 8; j++) {
            float4 a = np[j]; x[4*j]=a.x; x[4*j+1]=a.y; x[4*j+2]=a.z; x[4*j+3]=a.w;
            float4 pb = pp[j]; x[32+4*j]=pb.x; x[32+4*j+1]=pb.y; x[32+4*j+2]=pb.z; x[32+4*j+3]=pb.w;
        }
    } else {
#pragma unroll
        for (int j = 0; j < 64; j++) x[j] = 0.f;
    }
    writeRow64(sm+O_A, tid, x, true);
    __syncwarp();
    float accH[2][4][4] = {};
    warp_gemm<12,4>(su+O_A, su+O_W0, BP32, wid, lane, accH);
    __syncwarp();
    writeRow64(sm+O_A, tid, x, false);
    __syncwarp();
    float accO[2][4][4] = {};
    warp_gemm<12,4>(su+O_A, su+O_WS, BP32, wid, lane, accO);
    __syncwarp();
    fragToA<4>(sm+O_A, wid, lane, accH, b0, true);
    __syncwarp();
    warp_gemm<6,4>(su+O_A, su+O_W1, BP32, wid, lane, accO);
    __syncwarp();
    fragToA<4>(sm+O_A, wid, lane, accO, b1, false);
    __syncwarp();
    float accC[2][4][4] = {};
    warp_gemm<6,4>(su+O_A, su+O_FC, BP32, wid, lane, accC);
    fragStore(ctaBase, N, wid, lane, accC, sfb);
}

/* -------- output: CSR mean + transpose -------- */
__global__ void output_kernel(float* __restrict__ out, int total) {
    int t = blockIdx.x*blockDim.x + threadIdx.x;
    if (t >= total) return;
    int bg = t >> 5, ch = t & 31;
    int s = g_start[bg], n = g_hist[bg];
    float sum = 0.0f;
    for (int k = 0; k < n; k++) sum += g_net[(size_t)(s+k)*HID_ + ch];
    float mean = sum / fmaxf((float)n, 1.0f);
    int b = bg >> 15, g = bg & (G_ - 1);
    out[((size_t)b*HID_ + ch)*G_ + g] = mean;
}

/* -------- host -------- */
extern "C" void kernel_launch(void* const* d_in, const int* in_sizes, int n_in,
                              void* d_out, int out_size) {
    const float* p   = (const float*)d_in[0];
    const float* Wp  = (const float*)d_in[1];
    const float* Bp  = (const float*)d_in[2];
    const float* W0  = (const float*)d_in[3];
    const float* B0  = (const float*)d_in[4];
    const float* W1  = (const float*)d_in[5];
    const float* B1  = (const float*)d_in[6];
    const float* Ws  = (const float*)d_in[7];
    const float* Fc  = (const float*)d_in[8];
    const float* FcB = (const float*)d_in[9];
    float* out = (float*)d_out;

    int T = in_sizes[0] / (B_ * 3);
    int N = B_ * T;
    int nb = (N + BDIM - 1) / BDIM;

    cudaFuncSetAttribute(point0_kernel, cudaFuncAttributeMaxDynamicSharedMemorySize, SM_P0);
    cudaFuncSetAttribute(pool_block_kernel, cudaFuncAttributeMaxDynamicSharedMemorySize, SM_POOL);
    cudaFuncSetAttribute(final_kernel, cudaFuncAttributeMaxDynamicSharedMemorySize, SM_FIN);

    float* cellA; cudaGetSymbolAddress((void**)&cellA, g_cellA);
    float* cellB; cudaGetSymbolAddress((void**)&cellB, g_cellB);

    zero_hist_kernel<<<64, 256>>>();
    index_hist_kernel<<<nb, BDIM>>>(p, T, N);
    scan_kernel<<<1, 1024>>>();
    perm_kernel<<<nb, BDIM>>>(p, N);

    point0_kernel<<<nb, BDIM, SM_P0>>>(Wp, Bp, W0, B0, W1, B1, Ws, N);
    maxpool_kernel<<<BG_*8/256, 256>>>(cellA);

    pool_block_kernel<<<nb, BDIM, SM_POOL>>>(W0 + 1*64*HID_, B0 + 1*HID_,
        W1 + 1*HID_*HID_, B1 + 1*HID_, Ws + 1*64*HID_, cellA, N);
    maxpool_kernel<<<BG_*8/256, 256>>>(cellB);

    pool_block_kernel<<<nb, BDIM, SM_POOL>>>(W0 + 2*64*HID_, B0 + 2*HID_,
        W1 + 2*HID_*HID_, B1 + 2*HID_, Ws + 2*64*HID_, cellB, N);
    maxpool_kernel<<<BG_*8/256, 256>>>(cellA);

    pool_block_kernel<<<nb, BDIM, SM_POOL>>>(W0 + 3*64*HID_, B0 + 3*HID_,
        W1 + 3*HID_*HID_, B1 + 3*HID_, Ws + 3*64*HID_, cellA, N);
    maxpool_kernel<<<BG_*8/256, 256>>>(cellB);

    final_kernel<<<nb, BDIM, SM_FIN>>>(W0 + 4*64*HID_, B0 + 4*HID_,
        W1 + 4*HID_*HID_, B1 + 4*HID_, Ws + 4*64*HID_, Fc, FcB, cellB, N);

    output_kernel<<<(out_size + 255)/256, 256>>>(out, out_size);
}